// round 13
// baseline (speedup 1.0000x reference)
#include <cuda_runtime.h>
#include <cuda_bf16.h>
#include <math_constants.h>

// Fused greedy CTC decode — final locked configuration.
//   index[t] = argmax_v emission[t, v]  (first occurrence on ties)
//   char[t]  = -1 if index==0 ; index-1 if index>1 ; 0 if index==1
//   keep[t]  = (char[t] != char[t-1]) && (char[t] != -1)   (char[-1] := -2)
// Output (float32): [0..T) = (float)index, [T..2T) = keep (0.0/1.0).
//
// Nine structural variants (occ 36-91%, LDG vs cp.async.bulk, deep vs
// REDUX reduce, 1 vs 2 waves, ILP 1/2) all plateau at ~5.3-5.8 TB/s:
// the streaming-read BW ceiling is path-independent (~72% of spec).
// This is the best-measured core (R4: 24.03us kernel, DRAM 72.9%):
// 8 warps x 4 rows = 32 rows/block, grid 2048, chained low-register
// compares + shfl-pair argmax reduce (~30 regs -> ~89% occupancy).
// Refinements: boundary predecessor row issued BEFORE the owning warp's
// main rows (overlap, no straggler warp), coalesced smem-staged epilogue.

static constexpr int V = 512;
static constexpr int WARPS = 8;
static constexpr int R = 4;                         // rows per warp
static constexpr int ROWS_PER_BLOCK = WARPS * R;    // 32

__device__ __forceinline__ void cmp4(const float4 v, int e, float& best, int& bidx)
{
    if (v.x > best) { best = v.x; bidx = e;     }
    if (v.y > best) { best = v.y; bidx = e + 1; }
    if (v.z > best) { best = v.z; bidx = e + 2; }
    if (v.w > best) { best = v.w; bidx = e + 3; }
}

// Warp argmax of one row; returns first-occurrence argmax (uniform).
__device__ __forceinline__ int warp_argmax_row(const float* __restrict__ em,
                                               int row, int lane)
{
    const float4* __restrict__ p =
        reinterpret_cast<const float4*>(em + (size_t)row * V);

    float best = -CUDART_INF_F;
    int   bidx = 0;

    // 512 floats / warp: lane reads float4 at elements {lane*4 + c*128}.
    // Each warp-load is 512 contiguous bytes; loads consumed in order so
    // registers recycle (~30 regs total). Indices ascend within a lane,
    // so strict '>' keeps the first occurrence.
#pragma unroll
    for (int c = 0; c < 4; ++c)
        cmp4(p[lane + c * 32], lane * 4 + c * 128, best, bidx);

    // Shfl-pair reduce; on equal values take the smaller index
    // (matches jnp.argmax first-occurrence semantics).
#pragma unroll
    for (int off = 16; off; off >>= 1) {
        float om = __shfl_xor_sync(0xFFFFFFFFu, best, off);
        int   oi = __shfl_xor_sync(0xFFFFFFFFu, bidx, off);
        if (om > best || (om == best && oi < bidx)) { best = om; bidx = oi; }
    }
    return bidx;    // uniform across the warp
}

__device__ __forceinline__ int ctc_char(int i)
{
    return (i == 0) ? -1 : ((i > 1) ? i - 1 : 0);
}

__global__ __launch_bounds__(WARPS * 32, 8)
void ctc_fused_kernel(const float* __restrict__ em,
                      float* __restrict__ out_index,
                      float* __restrict__ out_keep,
                      int T)
{
    __shared__ int idx_s[ROWS_PER_BLOCK];
    __shared__ int ch[ROWS_PER_BLOCK + 1];   // ch[0] = char of row base-1

    const int warp = threadIdx.x >> 5;
    const int lane = threadIdx.x & 31;
    const int base = blockIdx.x * ROWS_PER_BLOCK;

    // Warp 0 resolves the block-boundary predecessor row FIRST so its
    // loads overlap the main rows instead of trailing them.
    if (warp == 0) {
        if (base == 0) {
            if (lane == 0) ch[0] = -2;           // char[-1] sentinel
        } else {
            const int bi = warp_argmax_row(em, base - 1, lane);
            if (lane == 0) ch[0] = ctc_char(bi);
        }
    }

    // 4 rows per warp.
#pragma unroll
    for (int j = 0; j < R; ++j) {
        const int local = warp * R + j;
        const int bidx  = warp_argmax_row(em, base + local, lane);
        if (lane == 0) {
            idx_s[local]  = bidx;
            ch[1 + local] = ctc_char(bidx);
        }
    }
    __syncthreads();

    // Coalesced epilogue: threads 0..31 write index, 32..63 write keep.
    if (threadIdx.x < ROWS_PER_BLOCK) {
        out_index[base + threadIdx.x] = (float)idx_s[threadIdx.x];
    } else if (threadIdx.x < 2 * ROWS_PER_BLOCK) {
        const int l = threadIdx.x - ROWS_PER_BLOCK;
        const int c  = ch[l + 1];
        const int pc = ch[l];
        out_keep[base + l] = (c != pc && c != -1) ? 1.0f : 0.0f;
    }
}

extern "C" void kernel_launch(void* const* d_in, const int* in_sizes, int n_in,
                              void* d_out, int out_size)
{
    const float* em = (const float*)d_in[0];
    const int T = in_sizes[0] / V;           // 65536 (divisible by 32)

    float* out       = (float*)d_out;
    float* out_index = out;
    float* out_keep  = out + T;

    const int grid = T / ROWS_PER_BLOCK;     // 2048
    ctc_fused_kernel<<<grid, WARPS * 32>>>(em, out_index, out_keep, T);
}

// round 14
// speedup vs baseline: 1.0918x; 1.0918x over previous
#include <cuda_runtime.h>
#include <cuda_bf16.h>
#include <math_constants.h>

// Fused greedy CTC decode — final configuration (best reproducible
// measurement: 25.056us total / 24.384us kernel, DRAM ~72%).
//   index[t] = argmax_v emission[t, v]  (first occurrence on ties)
//   char[t]  = -1 if index==0 ; index-1 if index>1 ; 0 if index==1
//   keep[t]  = (char[t] != char[t-1]) && (char[t] != -1)   (char[-1] := -2)
// Output (float32): [0..T) = (float)index, [T..2T) = keep (0.0/1.0).
//
// Ten structural variants (occ 36-91%, LDG vs cp.async.bulk, chained+shfl
// vs fmaxf-tree+REDUX argmax, 1 vs 2 waves, ILP 1/2, cache hints) plateau
// at ~5.3-5.8 TB/s: the streaming-read BW ceiling is path-independent.
// Head-to-head (R12 vs R13) the fmaxf-tree + REDUX argmax core is the
// faster one (24.38 vs 25.82us kernel) despite lower occupancy.
// 8 warps x 4 rows = 32 rows/block, grid 2048. Warp 0 resolves the
// block-boundary predecessor row first; coalesced smem-staged epilogue.

static constexpr int V = 512;
static constexpr int WARPS = 8;
static constexpr int R = 4;                         // rows per warp
static constexpr int ROWS_PER_BLOCK = WARPS * R;    // 32

// Strictly monotone float -> uint map (order- and equality-preserving).
__device__ __forceinline__ unsigned mono(float f)
{
    unsigned u = __float_as_uint(f);
    return u ^ ((unsigned)((int)u >> 31) | 0x80000000u);
}

// Inverse of mono().
__device__ __forceinline__ float inv_mono(unsigned k)
{
    unsigned u = k ^ ((~(unsigned)((int)k >> 31)) | 0x80000000u);
    return __uint_as_float(u);
}

// Warp argmax of one row; returns first-occurrence argmax (uniform).
__device__ __forceinline__ int warp_argmax_row(const float* __restrict__ em,
                                               int row, int lane)
{
    const float4* __restrict__ p =
        reinterpret_cast<const float4*>(em + (size_t)row * V);

    // Lane covers elements {lane*4 + c*128 + k}, c=0..3, k=0..3.
    float4 v0 = p[lane];
    float4 v1 = p[lane + 32];
    float4 v2 = p[lane + 64];
    float4 v3 = p[lane + 96];

    // Shallow max tree over the 16 lane-local values (FMA pipe).
    float m01 = fmaxf(fmaxf(v0.x, v0.y), fmaxf(v0.z, v0.w));
    float m23 = fmaxf(fmaxf(v1.x, v1.y), fmaxf(v1.z, v1.w));
    float m45 = fmaxf(fmaxf(v2.x, v2.y), fmaxf(v2.z, v2.w));
    float m67 = fmaxf(fmaxf(v3.x, v3.y), fmaxf(v3.z, v3.w));
    float lmax = fmaxf(fmaxf(m01, m23), fmaxf(m45, m67));

    // Warp max in one REDUX.
    const unsigned wkey = __reduce_max_sync(0xFFFFFFFFu, mono(lmax));
    const float wm = inv_mono(wkey);

    // First-occurrence index: independent equality-selects, then min tree.
    const int e0 = lane * 4, e1 = e0 + 128, e2 = e0 + 256, e3 = e0 + 384;
    const int BIG = 0x7FFFFFFF;
    int c0  = (v0.x == wm) ? e0     : BIG;
    int c1  = (v0.y == wm) ? e0 + 1 : BIG;
    int c2  = (v0.z == wm) ? e0 + 2 : BIG;
    int c3  = (v0.w == wm) ? e0 + 3 : BIG;
    int c4  = (v1.x == wm) ? e1     : BIG;
    int c5  = (v1.y == wm) ? e1 + 1 : BIG;
    int c6  = (v1.z == wm) ? e1 + 2 : BIG;
    int c7  = (v1.w == wm) ? e1 + 3 : BIG;
    int c8  = (v2.x == wm) ? e2     : BIG;
    int c9  = (v2.y == wm) ? e2 + 1 : BIG;
    int c10 = (v2.z == wm) ? e2 + 2 : BIG;
    int c11 = (v2.w == wm) ? e2 + 3 : BIG;
    int c12 = (v3.x == wm) ? e3     : BIG;
    int c13 = (v3.y == wm) ? e3 + 1 : BIG;
    int c14 = (v3.z == wm) ? e3 + 2 : BIG;
    int c15 = (v3.w == wm) ? e3 + 3 : BIG;

    int a = min(min(min(c0, c1), min(c2, c3)), min(min(c4, c5), min(c6, c7)));
    int b = min(min(min(c8, c9), min(c10, c11)),
                min(min(c12, c13), min(c14, c15)));
    const int cand = min(a, b);

    return (int)__reduce_min_sync(0xFFFFFFFFu, (unsigned)cand);
}

__device__ __forceinline__ int ctc_char(int i)
{
    return (i == 0) ? -1 : ((i > 1) ? i - 1 : 0);
}

__global__ __launch_bounds__(WARPS * 32)
void ctc_fused_kernel(const float* __restrict__ em,
                      float* __restrict__ out_index,
                      float* __restrict__ out_keep,
                      int T)
{
    __shared__ int idx_s[ROWS_PER_BLOCK];
    __shared__ int ch[ROWS_PER_BLOCK + 1];   // ch[0] = char of row base-1

    const int warp = threadIdx.x >> 5;
    const int lane = threadIdx.x & 31;
    const int base = blockIdx.x * ROWS_PER_BLOCK;

    // Warp 0 resolves the block-boundary predecessor row FIRST, so its
    // loads overlap with the other warps' main rows.
    if (warp == 0) {
        if (base == 0) {
            if (lane == 0) ch[0] = -2;           // char[-1] sentinel
        } else {
            const int bi = warp_argmax_row(em, base - 1, lane);
            if (lane == 0) ch[0] = ctc_char(bi);
        }
    }

#pragma unroll
    for (int j = 0; j < R; ++j) {
        const int local = warp * R + j;
        const int bidx  = warp_argmax_row(em, base + local, lane);
        if (lane == 0) {
            idx_s[local]  = bidx;
            ch[1 + local] = ctc_char(bidx);
        }
    }
    __syncthreads();

    // Coalesced epilogue: threads 0..31 write index, 32..63 write keep.
    if (threadIdx.x < ROWS_PER_BLOCK) {
        out_index[base + threadIdx.x] = (float)idx_s[threadIdx.x];
    } else if (threadIdx.x < 2 * ROWS_PER_BLOCK) {
        const int l = threadIdx.x - ROWS_PER_BLOCK;
        const int c  = ch[l + 1];
        const int pc = ch[l];
        out_keep[base + l] = (c != pc && c != -1) ? 1.0f : 0.0f;
    }
}

extern "C" void kernel_launch(void* const* d_in, const int* in_sizes, int n_in,
                              void* d_out, int out_size)
{
    const float* em = (const float*)d_in[0];
    const int T = in_sizes[0] / V;           // 65536 (divisible by 32)

    float* out       = (float*)d_out;
    float* out_index = out;
    float* out_keep  = out + T;

    const int grid = T / ROWS_PER_BLOCK;     // 2048
    ctc_fused_kernel<<<grid, WARPS * 32>>>(em, out_index, out_keep, T);
}